// round 13
// baseline (speedup 1.0000x reference)
#include <cuda_runtime.h>
#include <cuda_fp16.h>
#include <math.h>
#include <stdint.h>

typedef __half f16;
typedef unsigned int uint32;

// ============================ scratch =================================
__device__ f16   Xh[8192 * 1024];
__device__ f16   Wth[3 * 256 * 1024], Wtl[3 * 256 * 1024];   // W^T [proj][n][k]
__device__ f16   Qh[2 * 4096 * 256];
__device__ f16   Kh[2 * 4096 * 256];
__device__ f16   Vh[2 * 4096 * 256];
__device__ float OPart[2ull * 64 * 4 * 64 * 256];            // split-K partials
__device__ float MPart[2 * 64 * 4 * 64];
__device__ float LPart[2 * 64 * 4 * 64];

// ============================ helpers =================================
__device__ __forceinline__ void split2(float x, f16& h, f16& l) {
    h = __float2half(x);
    l = __float2half(x - __half2float(h));
}
__device__ __forceinline__ uint32 pk(f16 a, f16 b) {
    __half2 v(a, b);
    return *(uint32*)&v;
}
__device__ __forceinline__ void mma_f16(float c[4], const uint32 a[4],
                                        const uint32 b[2]) {
    asm volatile(
        "mma.sync.aligned.m16n8k16.row.col.f32.f16.f16.f32 "
        "{%0,%1,%2,%3}, {%4,%5,%6,%7}, {%8,%9}, {%0,%1,%2,%3};"
        : "+f"(c[0]), "+f"(c[1]), "+f"(c[2]), "+f"(c[3])
        : "r"(a[0]), "r"(a[1]), "r"(a[2]), "r"(a[3]), "r"(b[0]), "r"(b[1]));
}
#define LDSM4(r0, r1, r2, r3, a)                                              \
    asm volatile("ldmatrix.sync.aligned.m8n8.x4.shared.b16 {%0,%1,%2,%3}, [%4];" \
                 : "=r"(r0), "=r"(r1), "=r"(r2), "=r"(r3) : "r"(a))
#define LDSM4T(r0, r1, r2, r3, a)                                             \
    asm volatile("ldmatrix.sync.aligned.m8n8.x4.trans.shared.b16 {%0,%1,%2,%3}, [%4];" \
                 : "=r"(r0), "=r"(r1), "=r"(r2), "=r"(r3) : "r"(a))
#define CPA16(dst, src)                                                       \
    asm volatile("cp.async.cg.shared.global [%0], [%1], 16;"                  \
                 :: "r"((uint32)(dst)), "l"(src))
#define CPA_COMMIT() asm volatile("cp.async.commit_group;")
#define CPA_WAIT(n)  asm volatile("cp.async.wait_group %0;" :: "n"(n))

// ======================================================================
// Projection GEMM: 2-pass fp16 split, cp.async double-buffered stages.
// ======================================================================
#define RS   72
#define PL   18432                  // bytes per plane
#define STG  (3 * PL)               // 55296 per stage
#define SMEM_GEMM (2 * STG)         // 110592 -> 2 CTAs/SM

__global__ __launch_bounds__(256, 2) void proj_mma() {
    extern __shared__ char smem[];
    const uint32 smb = (uint32)__cvta_generic_to_shared(smem);
    const int m0 = (blockIdx.x >> 1) * 128;
    const int nb = blockIdx.x & 1;
    const int pj = blockIdx.y;

    const f16* Ag  = Xh + (size_t)m0 * 1024;
    const f16* Bhg = Wth + pj * 262144 + (size_t)(nb * 128) * 1024;
    const f16* Blg = Wtl + pj * 262144 + (size_t)(nb * 128) * 1024;

    const int t = threadIdx.x, wid = t >> 5, lane = t & 31;
    const int wm = wid >> 2, wn = wid & 3;
    const int gr = lane >> 2, tc = lane & 3;

    int row[4], c8[4];
#pragma unroll
    for (int i = 0; i < 4; i++) { int u = t + 256 * i; row[i] = u >> 3; c8[i] = u & 7; }

#define ISSUE(ch, buf) {                                                      \
    const int k0_ = (ch) * 64;                                                \
    const uint32 bb_ = smb + (buf) * STG;                                     \
    _Pragma("unroll") for (int i_ = 0; i_ < 4; i_++) {                        \
        uint32 off_ = row[i_] * 144 + c8[i_] * 16;                            \
        CPA16(bb_ + off_,          Ag  + (size_t)row[i_] * 1024 + k0_ + c8[i_] * 8); \
        CPA16(bb_ + PL + off_,     Bhg + (size_t)row[i_] * 1024 + k0_ + c8[i_] * 8); \
        CPA16(bb_ + 2 * PL + off_, Blg + (size_t)row[i_] * 1024 + k0_ + c8[i_] * 8); \
    }                                                                         \
    CPA_COMMIT(); }

    float acc[16][4];
#pragma unroll
    for (int i = 0; i < 16; i++)
#pragma unroll
        for (int j = 0; j < 4; j++) acc[i][j] = 0.f;

    ISSUE(0, 0);
    for (int ch = 0; ch < 16; ch++) {
        if (ch + 1 < 16) { ISSUE(ch + 1, (ch + 1) & 1); CPA_WAIT(1); }
        else             { CPA_WAIT(0); }
        __syncthreads();   // stage (ch&1) fully visible

        const char* buf = smem + (ch & 1) * STG;
        const f16* sAh = (const f16*)(buf);
        const f16* sBh = (const f16*)(buf + PL);
        const f16* sBl = (const f16*)(buf + 2 * PL);

#pragma unroll
        for (int ks = 0; ks < 4; ks++) {
            uint32 ah[4][4], bh[4][2], bl[4][2];
#pragma unroll
            for (int mf = 0; mf < 4; mf++) {
                int o = (wm * 64 + mf * 16 + gr) * RS + ks * 16 + 2 * tc;
                ah[mf][0] = *(const uint32*)(sAh + o);
                ah[mf][1] = *(const uint32*)(sAh + o + 8 * RS);
                ah[mf][2] = *(const uint32*)(sAh + o + 8);
                ah[mf][3] = *(const uint32*)(sAh + o + 8 * RS + 8);
            }
#pragma unroll
            for (int nf = 0; nf < 4; nf++) {
                int o = (wn * 32 + nf * 8 + gr) * RS + ks * 16 + 2 * tc;
                bh[nf][0] = *(const uint32*)(sBh + o);
                bh[nf][1] = *(const uint32*)(sBh + o + 8);
                bl[nf][0] = *(const uint32*)(sBl + o);
                bl[nf][1] = *(const uint32*)(sBl + o + 8);
            }
#pragma unroll
            for (int mf = 0; mf < 4; mf++)
#pragma unroll
                for (int nf = 0; nf < 4; nf++) {
                    mma_f16(acc[mf * 4 + nf], ah[mf], bh[nf]);
                    mma_f16(acc[mf * 4 + nf], ah[mf], bl[nf]);
                }
        }
        __syncthreads();   // stage reads done before refill (ch+2)
    }
#undef ISSUE

    f16* dh = (pj == 0) ? Qh : (pj == 1) ? Kh : Vh;
#pragma unroll
    for (int mf = 0; mf < 4; mf++)
#pragma unroll
        for (int nf = 0; nf < 4; nf++)
#pragma unroll
            for (int h = 0; h < 2; h++) {
                int m = m0 + wm * 64 + mf * 16 + gr + 8 * h;
                int n = nb * 128 + wn * 32 + nf * 8 + 2 * tc;
                int s = m >> 1, b = m & 1;
                float v0 = acc[mf * 4 + nf][2 * h];
                float v1 = acc[mf * 4 + nf][2 * h + 1];
                size_t o = ((size_t)b * 4096 + s) * 256 + n;
                *(uint32*)(dh + o) = pk(__float2half(v0), __float2half(v1));
            }
}

// ============================ kernel 1: convert X (hi only) ===========
__global__ __launch_bounds__(256) void cvt_x(const float* __restrict__ X) {
    const int N4 = 8192 * 1024 / 4;
    for (int i = blockIdx.x * 256 + threadIdx.x; i < N4; i += 2048 * 256) {
        float4 x = ((const float4*)X)[i];
        ((uint2*)Xh)[i] = make_uint2(
            pk(__float2half(x.x), __float2half(x.y)),
            pk(__float2half(x.z), __float2half(x.w)));
    }
}

// ============================ kernel 2: convert+transpose W ===========
__global__ void cvt_w(const float* __restrict__ Wq, const float* __restrict__ Wk,
                      const float* __restrict__ Wv) {
    __shared__ float tile[32][33];
    const int pj = blockIdx.z;
    const float* W = (pj == 0) ? Wq : (pj == 1) ? Wk : Wv;
    const int k0 = blockIdx.x * 32, n0 = blockIdx.y * 32;
    const int tx = threadIdx.x, ty = threadIdx.y;
#pragma unroll
    for (int i = 0; i < 4; i++)
        tile[ty + 8 * i][tx] = W[(k0 + ty + 8 * i) * 256 + n0 + tx];
    __syncthreads();
#pragma unroll
    for (int i = 0; i < 4; i++) {
        int n = n0 + ty + 8 * i;
        f16 h, l;
        split2(tile[tx][ty + 8 * i], h, l);
        Wth[pj * 262144 + n * 1024 + k0 + tx] = h;
        Wtl[pj * 262144 + n * 1024 + k0 + tx] = l;
    }
}

// ======================================================================
// Kernel 4: fused flash attention — R12 + K pipelined one iteration
// ahead (K(kt+1) issued right after all warps finish reading K(kt)).
// Group FIFO: K(kt), V(kt), K(kt+1), ... wait(1) pends exactly K(kt).
// ======================================================================
#define SQ_  0                      // Q: 64 rows x 528 B   = 33792
#define SK_  33792                  // K: 128 rows x 528 B  = 67584
#define SV_  101376                 // V: 128 rows x 528 B  = 67584
#define SP_  168960                 // P: 64 x 272 B        = 17408
#define SMX_ 186368                 // 64 x 4 floats
#define FSZ  187392

__global__ __launch_bounds__(256) void fa_mma() {
    extern __shared__ char sm[];
    const int t = threadIdx.x, wid = t >> 5, lane = t & 31;
    const int wm = wid >> 2, wn = wid & 3;
    const int gr = lane >> 2, tc = lane & 3;
    const int b = blockIdx.y;
    const uint32 smb = (uint32)__cvta_generic_to_shared(sm);

    const uint32 aoffQ = (lane & 15) * 528 + (lane >> 4) * 16;
    const uint32 aoffP = (lane & 15) * 272 + (lane >> 4) * 16;
    const uint32 boffK = ((lane & 7) + ((lane >> 4) & 1) * 8) * 528 + ((lane >> 3) & 1) * 16;
    const uint32 boffV = ((lane & 7) + ((lane >> 3) & 1) * 8) * 528 + ((lane >> 4) & 1) * 16;

    // chunk decode (reversed: biggest qi first); CHUNK = 8 key-tiles
    const int n = 159 - blockIdx.x;
    int qi, c;
    if (n < 16)      { qi = n;                  c = 0; }
    else if (n < 48) { int m_ = n - 16; qi = 16 + (m_ >> 1); c = m_ & 1; }
    else if (n < 96) { int m_ = n - 48; qi = 32 + m_ / 3;    c = m_ % 3; }
    else             { int m_ = n - 96; qi = 48 + (m_ >> 2); c = m_ & 3; }

    const int kt_diag = qi >> 1;
    const int kt0 = c * 8;
    const int kt1 = min(kt0 + 8, kt_diag + 1);
    const int q0 = qi * 64;

    uint32* p32 = (uint32*)(sm + SP_);
    float* pmax = (float*)(sm + SMX_);

    // per-thread cp.async row mapping for K/V tiles
    int krow[16], kc16[16];
#pragma unroll
    for (int i = 0; i < 16; i++) { int u = t + 256 * i; krow[i] = u >> 5; kc16[i] = u & 31; }

#define ISSUE_K(kt_) {                                                        \
    _Pragma("unroll") for (int i_ = 0; i_ < 16; i_++)                         \
        CPA16(smb + SK_ + krow[i_] * 528 + kc16[i_] * 16,                     \
              Kh + ((size_t)(b * 4096 + (kt_) * 128 + krow[i_])) * 256 + kc16[i_] * 8); \
    CPA_COMMIT(); }
#define ISSUE_V(kt_) {                                                        \
    _Pragma("unroll") for (int i_ = 0; i_ < 16; i_++)                         \
        CPA16(smb + SV_ + krow[i_] * 528 + kc16[i_] * 16,                     \
              Vh + ((size_t)(b * 4096 + (kt_) * 128 + krow[i_])) * 256 + kc16[i_] * 8); \
    CPA_COMMIT(); }

    // ---- load Q once + prefetch first K ----
    ISSUE_K(kt0);
#pragma unroll
    for (int i = 0; i < 8; i++) {
        int u = t + 256 * i, row = u >> 5, c16 = u & 31;
        *(float4*)(sm + SQ_ + row * 528 + c16 * 16) =
            *(const float4*)(Qh + ((size_t)(b * 4096 + q0 + row)) * 256 + c16 * 8);
    }

    float acc_o[2][8][4];
#pragma unroll
    for (int mf = 0; mf < 2; mf++)
#pragma unroll
        for (int nf = 0; nf < 8; nf++)
#pragma unroll
            for (int ci = 0; ci < 4; ci++) acc_o[mf][nf][ci] = 0.f;
    float m[4] = {-INFINITY, -INFINITY, -INFINITY, -INFINITY};
    float l[4] = {0.f, 0.f, 0.f, 0.f};

    for (int kt = kt0; kt < kt1; kt++) {
        const bool diag = (kt == kt_diag);
        const bool last = (kt + 1 >= kt1);

        __syncthreads();   // prior PV reads done -> V buffer free (covers Q stores, iter 0)
        ISSUE_V(kt);
        CPA_WAIT(1);       // K(kt) landed (issued one iteration ago); V(kt) in flight
        __syncthreads();   // K visible

        // ---------------- S = Q K^T ----------------
        float acc_s[2][4][4];
#pragma unroll
        for (int mf = 0; mf < 2; mf++)
#pragma unroll
            for (int nf = 0; nf < 4; nf++)
#pragma unroll
                for (int ci = 0; ci < 4; ci++) acc_s[mf][nf][ci] = 0.f;

#pragma unroll
        for (int dc = 0; dc < 4; dc++)
#pragma unroll
            for (int ks = 0; ks < 4; ks++) {
                const uint32 kb = dc * 128 + ks * 32;
                uint32 ah[2][4], bh[4][2];
#pragma unroll
                for (int mf = 0; mf < 2; mf++)
                    LDSM4(ah[mf][0], ah[mf][1], ah[mf][2], ah[mf][3],
                          smb + SQ_ + (wm * 32 + mf * 16) * 528 + aoffQ + kb);
#pragma unroll
                for (int nfp = 0; nfp < 2; nfp++)
                    LDSM4(bh[2 * nfp][0], bh[2 * nfp][1],
                          bh[2 * nfp + 1][0], bh[2 * nfp + 1][1],
                          smb + SK_ + (wn * 32 + nfp * 16) * 528 + boffK + kb);
#pragma unroll
                for (int mf = 0; mf < 2; mf++)
#pragma unroll
                    for (int nf = 0; nf < 4; nf++)
                        mma_f16(acc_s[mf][nf], ah[mf], bh[nf]);
            }

        // ---------------- scale + mask + row-max ----------------
        float pm[4] = {-1e30f, -1e30f, -1e30f, -1e30f};
#pragma unroll
        for (int mf = 0; mf < 2; mf++)
#pragma unroll
            for (int nf = 0; nf < 4; nf++)
#pragma unroll
                for (int ci = 0; ci < 4; ci++) {
                    float s = acc_s[mf][nf][ci] * 0.0625f;
                    if (diag) {
                        int qg = q0 + wm * 32 + mf * 16 + gr + (ci >> 1) * 8;
                        int kg = kt * 128 + wn * 32 + nf * 8 + 2 * tc + (ci & 1);
                        if (kg > qg) s = -1e30f;
                    }
                    acc_s[mf][nf][ci] = s;
                    int ri = mf * 2 + (ci >> 1);
                    pm[ri] = fmaxf(pm[ri], s);
                }
#pragma unroll
        for (int i = 0; i < 4; i++) {
            pm[i] = fmaxf(pm[i], __shfl_xor_sync(~0u, pm[i], 1));
            pm[i] = fmaxf(pm[i], __shfl_xor_sync(~0u, pm[i], 2));
        }
        if (tc == 0) {
#pragma unroll
            for (int i = 0; i < 4; i++) {
                int row = wm * 32 + (i >> 1) * 16 + (i & 1) * 8 + gr;
                pmax[row * 4 + wn] = pm[i];
            }
        }
        __syncthreads();   // pmax visible; ALL warps done reading K(kt)

        if (!last) ISSUE_K(kt + 1);   // overlaps softmax + P-write + PV

        float alpha[4];
#pragma unroll
        for (int i = 0; i < 4; i++) {
            int row = wm * 32 + (i >> 1) * 16 + (i & 1) * 8 + gr;
            float mt = fmaxf(fmaxf(pmax[row * 4 + 0], pmax[row * 4 + 1]),
                             fmaxf(pmax[row * 4 + 2], pmax[row * 4 + 3]));
            float m_new = fmaxf(m[i], mt);
            alpha[i] = __expf(m[i] - m_new);
            m[i] = m_new;
            l[i] *= alpha[i];
        }
#pragma unroll
        for (int mf = 0; mf < 2; mf++)
#pragma unroll
            for (int nf = 0; nf < 8; nf++)
#pragma unroll
                for (int ci = 0; ci < 4; ci++)
                    acc_o[mf][nf][ci] *= alpha[mf * 2 + (ci >> 1)];

        // ---------------- exp -> P (fp16) into smem ----------------
#pragma unroll
        for (int mf = 0; mf < 2; mf++)
#pragma unroll
            for (int nf = 0; nf < 4; nf++)
#pragma unroll
                for (int h = 0; h < 2; h++) {
                    int ri = mf * 2 + h;
                    float p0 = __expf(acc_s[mf][nf][h * 2 + 0] - m[ri]);
                    float p1 = __expf(acc_s[mf][nf][h * 2 + 1] - m[ri]);
                    l[ri] += p0 + p1;
                    int row = wm * 32 + mf * 16 + h * 8 + gr;
                    p32[row * 68 + wn * 16 + nf * 4 + tc] =
                        pk(__float2half(p0), __float2half(p1));
                }
        // wait for V(kt): outstanding groups = {V(kt), K(kt+1)} or {V(kt)}
        if (!last) { CPA_WAIT(1); } else { CPA_WAIT(0); }
        __syncthreads();   // P + V visible

        // ---------------- PV (V frags via ldmatrix.trans) ----------------
#pragma unroll
        for (int kc = 0; kc < 2; kc++)
#pragma unroll
            for (int ks = 0; ks < 4; ks++) {
                const uint32 sb_ = (kc * 64 + ks * 16) * 528;
                const uint32 pb_ = kc * 128 + ks * 32;
                uint32 ah[2][4], bh[8][2];
#pragma unroll
                for (int mf = 0; mf < 2; mf++)
                    LDSM4(ah[mf][0], ah[mf][1], ah[mf][2], ah[mf][3],
                          smb + SP_ + (wm * 32 + mf * 16) * 272 + aoffP + pb_);
#pragma unroll
                for (int nfp = 0; nfp < 4; nfp++)
                    LDSM4T(bh[2 * nfp][0], bh[2 * nfp][1],
                           bh[2 * nfp + 1][0], bh[2 * nfp + 1][1],
                           smb + SV_ + sb_ + boffV + wn * 128 + nfp * 32);
#pragma unroll
                for (int mf = 0; mf < 2; mf++)
#pragma unroll
                    for (int nf = 0; nf < 8; nf++)
                        mma_f16(acc_o[mf][nf], ah[mf], bh[nf]);
            }
    }
#undef ISSUE_K
#undef ISSUE_V

    // ---------------- epilogue: reduce l, write partials ----------------
#pragma unroll
    for (int i = 0; i < 4; i++) {
        l[i] += __shfl_xor_sync(~0u, l[i], 1);
        l[i] += __shfl_xor_sync(~0u, l[i], 2);
    }
    __syncthreads();   // last PV reads + pmax reads done before reuse
    if (tc == 0) {
#pragma unroll
        for (int i = 0; i < 4; i++) {
            int row = wm * 32 + (i >> 1) * 16 + (i & 1) * 8 + gr;
            pmax[row * 4 + wn] = l[i];
        }
    }
    __syncthreads();

    const size_t pb = ((size_t)(b * 64 + qi) * 4 + c) * 64;
#pragma unroll
    for (int i = 0; i < 4; i++) {
        int row = wm * 32 + (i >> 1) * 16 + (i & 1) * 8 + gr;
        if (wn == 0 && tc == 0) {
            float lr = pmax[row * 4 + 0] + pmax[row * 4 + 1] +
                       pmax[row * 4 + 2] + pmax[row * 4 + 3];
            MPart[pb + row] = m[i];
            LPart[pb + row] = lr;
        }
    }
#pragma unroll
    for (int mf = 0; mf < 2; mf++)
#pragma unroll
        for (int h = 0; h < 2; h++) {
            int row = wm * 32 + mf * 16 + h * 8 + gr;
            float* orow = OPart + (pb + row) * 256;
#pragma unroll
            for (int nf = 0; nf < 8; nf++) {
                float2 v = make_float2(acc_o[mf][nf][h * 2 + 0],
                                       acc_o[mf][nf][h * 2 + 1]);
                *(float2*)(orow + wn * 64 + nf * 8 + 2 * tc) = v;
            }
        }
}

// ============================ kernel 5: combine =======================
__global__ __launch_bounds__(256) void combine_k(float* __restrict__ out) {
    const int t = threadIdx.x;
    const int R = blockIdx.x * 4 + (t >> 6);   // = q*2 + b
    const int q = R >> 1, b = R & 1;
    const int qi = q >> 6, r = q & 63;
    const int nc = (qi >> 4) + 1;
    const size_t cb = ((size_t)(b * 64 + qi) * 4) * 64 + r;

    float mx = -INFINITY;
    for (int c = 0; c < nc; c++) mx = fmaxf(mx, MPart[cb + (size_t)c * 64]);
    float w[4];
    float denom = 0.f;
    for (int c = 0; c < nc; c++) {
        w[c] = __expf(MPart[cb + (size_t)c * 64] - mx);
        denom += w[c] * LPart[cb + (size_t)c * 64];
    }
    const float inv = 1.f / denom;

    const int d = (t & 63) * 4;
    float4 acc = make_float4(0.f, 0.f, 0.f, 0.f);
    for (int c = 0; c < nc; c++) {
        const float4 v = *(const float4*)
            (OPart + (cb + (size_t)c * 64) * 256 + d);
        acc.x += w[c] * v.x; acc.y += w[c] * v.y;
        acc.z += w[c] * v.z; acc.w += w[c] * v.w;
    }
    acc.x *= inv; acc.y *= inv; acc.z *= inv; acc.w *= inv;
    *(float4*)(out + (size_t)R * 256 + d) = acc;
}

// ============================ launch ==================================
extern "C" void kernel_launch(void* const* d_in, const int* in_sizes, int n_in,
                              void* d_out, int out_size) {
    const float* x  = (const float*)d_in[0];
    const float* Wq = (const float*)d_in[2];
    const float* Wk = (const float*)d_in[3];
    const float* Wv = (const float*)d_in[4];
    float* out = (float*)d_out;

    cudaFuncSetAttribute(proj_mma, cudaFuncAttributeMaxDynamicSharedMemorySize, SMEM_GEMM);
    cudaFuncSetAttribute(fa_mma,   cudaFuncAttributeMaxDynamicSharedMemorySize, FSZ);

    cvt_x<<<2048, 256>>>(x);
    cvt_w<<<dim3(32, 8, 3), dim3(32, 8)>>>(Wq, Wk, Wv);
    proj_mma<<<dim3(128, 3), 256, SMEM_GEMM>>>();
    fa_mma<<<dim3(160, 2), 256, FSZ>>>();
    combine_k<<<2048, 256>>>(out);
}

// round 14
// speedup vs baseline: 1.0309x; 1.0309x over previous
#include <cuda_runtime.h>
#include <cuda_fp16.h>
#include <math.h>
#include <stdint.h>

typedef __half f16;
typedef unsigned int uint32;

// ============================ scratch =================================
__device__ f16   Xh[8192 * 1024];
__device__ f16   Wth[3 * 256 * 1024], Wtl[3 * 256 * 1024];   // W^T [proj][n][k]
__device__ f16   Qh[2 * 4096 * 256];
__device__ f16   Kh[2 * 4096 * 256];
__device__ f16   Vh[2 * 4096 * 256];
__device__ float OPart[2ull * 64 * 4 * 64 * 256];            // split-K partials
__device__ float MPart[2 * 64 * 4 * 64];
__device__ float LPart[2 * 64 * 4 * 64];

// ============================ helpers =================================
__device__ __forceinline__ void split2(float x, f16& h, f16& l) {
    h = __float2half(x);
    l = __float2half(x - __half2float(h));
}
__device__ __forceinline__ uint32 pk(f16 a, f16 b) {
    __half2 v(a, b);
    return *(uint32*)&v;
}
__device__ __forceinline__ void mma_f16(float c[4], const uint32 a[4],
                                        const uint32 b[2]) {
    asm volatile(
        "mma.sync.aligned.m16n8k16.row.col.f32.f16.f16.f32 "
        "{%0,%1,%2,%3}, {%4,%5,%6,%7}, {%8,%9}, {%0,%1,%2,%3};"
        : "+f"(c[0]), "+f"(c[1]), "+f"(c[2]), "+f"(c[3])
        : "r"(a[0]), "r"(a[1]), "r"(a[2]), "r"(a[3]), "r"(b[0]), "r"(b[1]));
}
#define LDSM4(r0, r1, r2, r3, a)                                              \
    asm volatile("ldmatrix.sync.aligned.m8n8.x4.shared.b16 {%0,%1,%2,%3}, [%4];" \
                 : "=r"(r0), "=r"(r1), "=r"(r2), "=r"(r3) : "r"(a))
#define LDSM4T(r0, r1, r2, r3, a)                                             \
    asm volatile("ldmatrix.sync.aligned.m8n8.x4.trans.shared.b16 {%0,%1,%2,%3}, [%4];" \
                 : "=r"(r0), "=r"(r1), "=r"(r2), "=r"(r3) : "r"(a))
#define CPA16(dst, src)                                                       \
    asm volatile("cp.async.cg.shared.global [%0], [%1], 16;"                  \
                 :: "r"((uint32)(dst)), "l"(src))
#define CPA_COMMIT() asm volatile("cp.async.commit_group;")
#define CPA_WAIT(n)  asm volatile("cp.async.wait_group %0;" :: "n"(n))

// ======================================================================
// Projection GEMM: 2-pass fp16 split, cp.async double-buffered stages.
// ======================================================================
#define RS   72
#define PL   18432                  // bytes per plane
#define STG  (3 * PL)               // 55296 per stage
#define SMEM_GEMM (2 * STG)         // 110592 -> 2 CTAs/SM

__global__ __launch_bounds__(256, 2) void proj_mma() {
    extern __shared__ char smem[];
    const uint32 smb = (uint32)__cvta_generic_to_shared(smem);
    const int m0 = (blockIdx.x >> 1) * 128;
    const int nb = blockIdx.x & 1;
    const int pj = blockIdx.y;

    const f16* Ag  = Xh + (size_t)m0 * 1024;
    const f16* Bhg = Wth + pj * 262144 + (size_t)(nb * 128) * 1024;
    const f16* Blg = Wtl + pj * 262144 + (size_t)(nb * 128) * 1024;

    const int t = threadIdx.x, wid = t >> 5, lane = t & 31;
    const int wm = wid >> 2, wn = wid & 3;
    const int gr = lane >> 2, tc = lane & 3;

    int row[4], c8[4];
#pragma unroll
    for (int i = 0; i < 4; i++) { int u = t + 256 * i; row[i] = u >> 3; c8[i] = u & 7; }

#define ISSUE(ch, buf) {                                                      \
    const int k0_ = (ch) * 64;                                                \
    const uint32 bb_ = smb + (buf) * STG;                                     \
    _Pragma("unroll") for (int i_ = 0; i_ < 4; i_++) {                        \
        uint32 off_ = row[i_] * 144 + c8[i_] * 16;                            \
        CPA16(bb_ + off_,          Ag  + (size_t)row[i_] * 1024 + k0_ + c8[i_] * 8); \
        CPA16(bb_ + PL + off_,     Bhg + (size_t)row[i_] * 1024 + k0_ + c8[i_] * 8); \
        CPA16(bb_ + 2 * PL + off_, Blg + (size_t)row[i_] * 1024 + k0_ + c8[i_] * 8); \
    }                                                                         \
    CPA_COMMIT(); }

    float acc[16][4];
#pragma unroll
    for (int i = 0; i < 16; i++)
#pragma unroll
        for (int j = 0; j < 4; j++) acc[i][j] = 0.f;

    ISSUE(0, 0);
    for (int ch = 0; ch < 16; ch++) {
        if (ch + 1 < 16) { ISSUE(ch + 1, (ch + 1) & 1); CPA_WAIT(1); }
        else             { CPA_WAIT(0); }
        __syncthreads();   // stage (ch&1) fully visible

        const char* buf = smem + (ch & 1) * STG;
        const f16* sAh = (const f16*)(buf);
        const f16* sBh = (const f16*)(buf + PL);
        const f16* sBl = (const f16*)(buf + 2 * PL);

#pragma unroll
        for (int ks = 0; ks < 4; ks++) {
            uint32 ah[4][4], bh[4][2], bl[4][2];
#pragma unroll
            for (int mf = 0; mf < 4; mf++) {
                int o = (wm * 64 + mf * 16 + gr) * RS + ks * 16 + 2 * tc;
                ah[mf][0] = *(const uint32*)(sAh + o);
                ah[mf][1] = *(const uint32*)(sAh + o + 8 * RS);
                ah[mf][2] = *(const uint32*)(sAh + o + 8);
                ah[mf][3] = *(const uint32*)(sAh + o + 8 * RS + 8);
            }
#pragma unroll
            for (int nf = 0; nf < 4; nf++) {
                int o = (wn * 32 + nf * 8 + gr) * RS + ks * 16 + 2 * tc;
                bh[nf][0] = *(const uint32*)(sBh + o);
                bh[nf][1] = *(const uint32*)(sBh + o + 8);
                bl[nf][0] = *(const uint32*)(sBl + o);
                bl[nf][1] = *(const uint32*)(sBl + o + 8);
            }
#pragma unroll
            for (int mf = 0; mf < 4; mf++)
#pragma unroll
                for (int nf = 0; nf < 4; nf++) {
                    mma_f16(acc[mf * 4 + nf], ah[mf], bh[nf]);
                    mma_f16(acc[mf * 4 + nf], ah[mf], bl[nf]);
                }
        }
        __syncthreads();   // stage reads done before refill (ch+2)
    }
#undef ISSUE

    f16* dh = (pj == 0) ? Qh : (pj == 1) ? Kh : Vh;
#pragma unroll
    for (int mf = 0; mf < 4; mf++)
#pragma unroll
        for (int nf = 0; nf < 4; nf++)
#pragma unroll
            for (int h = 0; h < 2; h++) {
                int m = m0 + wm * 64 + mf * 16 + gr + 8 * h;
                int n = nb * 128 + wn * 32 + nf * 8 + 2 * tc;
                int s = m >> 1, b = m & 1;
                float v0 = acc[mf * 4 + nf][2 * h];
                float v1 = acc[mf * 4 + nf][2 * h + 1];
                size_t o = ((size_t)b * 4096 + s) * 256 + n;
                *(uint32*)(dh + o) = pk(__float2half(v0), __float2half(v1));
            }
}

// ============== kernel 1: merged convert X + convert/transpose W ======
__global__ __launch_bounds__(256) void cvt_xw(const float* __restrict__ X,
                                              const float* __restrict__ Wq,
                                              const float* __restrict__ Wk,
                                              const float* __restrict__ Wv) {
    const int t = threadIdx.x;
    const int bid = blockIdx.x;
    if (bid < 2048) {
        // ---- X: fp32 -> fp16 hi plane ----
        const int N4 = 8192 * 1024 / 4;
        for (int i = bid * 256 + t; i < N4; i += 2048 * 256) {
            float4 x = ((const float4*)X)[i];
            ((uint2*)Xh)[i] = make_uint2(
                pk(__float2half(x.x), __float2half(x.y)),
                pk(__float2half(x.z), __float2half(x.w)));
        }
    } else {
        // ---- W: fp32 -> split fp16 hi/lo, transposed to [n][k] ----
        __shared__ float tile[32][33];
        const int wb = bid - 2048;          // 0..767
        const int pj = wb >> 8;             // /256
        const int rem = wb & 255;
        const int k0 = (rem >> 3) * 32;     // 32 k-blocks
        const int n0 = (rem & 7) * 32;      // 8 n-blocks
        const float* W = (pj == 0) ? Wq : (pj == 1) ? Wk : Wv;
        const int tx = t & 31, ty = t >> 5; // (32, 8)
#pragma unroll
        for (int i = 0; i < 4; i++)
            tile[ty + 8 * i][tx] = W[(k0 + ty + 8 * i) * 256 + n0 + tx];
        __syncthreads();
#pragma unroll
        for (int i = 0; i < 4; i++) {
            int n = n0 + ty + 8 * i;
            f16 h, l;
            split2(tile[tx][ty + 8 * i], h, l);
            Wth[pj * 262144 + n * 1024 + k0 + tx] = h;
            Wtl[pj * 262144 + n * 1024 + k0 + tx] = l;
        }
    }
}

// ======================================================================
// Kernel 4: fused flash attention — exact R12 form (best measured: 87.0us).
// cp.async split-wait: K awaited before S, V awaited only before PV.
// ======================================================================
#define SQ_  0                      // Q: 64 rows x 528 B   = 33792
#define SK_  33792                  // K: 128 rows x 528 B  = 67584
#define SV_  101376                 // V: 128 rows x 528 B  = 67584
#define SP_  168960                 // P: 64 x 272 B        = 17408
#define SMX_ 186368                 // 64 x 4 floats
#define FSZ  187392

__global__ __launch_bounds__(256) void fa_mma() {
    extern __shared__ char sm[];
    const int t = threadIdx.x, wid = t >> 5, lane = t & 31;
    const int wm = wid >> 2, wn = wid & 3;
    const int gr = lane >> 2, tc = lane & 3;
    const int b = blockIdx.y;
    const uint32 smb = (uint32)__cvta_generic_to_shared(sm);

    const uint32 aoffQ = (lane & 15) * 528 + (lane >> 4) * 16;
    const uint32 aoffP = (lane & 15) * 272 + (lane >> 4) * 16;
    const uint32 boffK = ((lane & 7) + ((lane >> 4) & 1) * 8) * 528 + ((lane >> 3) & 1) * 16;
    const uint32 boffV = ((lane & 7) + ((lane >> 3) & 1) * 8) * 528 + ((lane >> 4) & 1) * 16;

    // chunk decode (reversed: biggest qi first); CHUNK = 8 key-tiles
    const int n = 159 - blockIdx.x;
    int qi, c;
    if (n < 16)      { qi = n;                  c = 0; }
    else if (n < 48) { int m_ = n - 16; qi = 16 + (m_ >> 1); c = m_ & 1; }
    else if (n < 96) { int m_ = n - 48; qi = 32 + m_ / 3;    c = m_ % 3; }
    else             { int m_ = n - 96; qi = 48 + (m_ >> 2); c = m_ & 3; }

    const int kt_diag = qi >> 1;
    const int kt0 = c * 8;
    const int kt1 = min(kt0 + 8, kt_diag + 1);
    const int q0 = qi * 64;

    uint32* p32 = (uint32*)(sm + SP_);
    float* pmax = (float*)(sm + SMX_);

    // ---- load Q once (64 x 256 f16) ----
#pragma unroll
    for (int i = 0; i < 8; i++) {
        int u = t + 256 * i, row = u >> 5, c16 = u & 31;
        *(float4*)(sm + SQ_ + row * 528 + c16 * 16) =
            *(const float4*)(Qh + ((size_t)(b * 4096 + q0 + row)) * 256 + c16 * 8);
    }

    float acc_o[2][8][4];
#pragma unroll
    for (int mf = 0; mf < 2; mf++)
#pragma unroll
        for (int nf = 0; nf < 8; nf++)
#pragma unroll
            for (int ci = 0; ci < 4; ci++) acc_o[mf][nf][ci] = 0.f;
    float m[4] = {-INFINITY, -INFINITY, -INFINITY, -INFINITY};
    float l[4] = {0.f, 0.f, 0.f, 0.f};

    for (int kt = kt0; kt < kt1; kt++) {
        const bool diag = (kt == kt_diag);

        __syncthreads();   // prior iter's smem reads done (covers Q stores, iter 0)
        // K group, then V group (separate commits)
#pragma unroll
        for (int i = 0; i < 16; i++) {
            int u = t + 256 * i, row = u >> 5, c16 = u & 31;
            CPA16(smb + SK_ + row * 528 + c16 * 16,
                  Kh + ((size_t)(b * 4096 + kt * 128 + row)) * 256 + c16 * 8);
        }
        CPA_COMMIT();
#pragma unroll
        for (int i = 0; i < 16; i++) {
            int u = t + 256 * i, row = u >> 5, c16 = u & 31;
            CPA16(smb + SV_ + row * 528 + c16 * 16,
                  Vh + ((size_t)(b * 4096 + kt * 128 + row)) * 256 + c16 * 8);
        }
        CPA_COMMIT();
        CPA_WAIT(1);       // K landed; V still in flight
        __syncthreads();

        // ---------------- S = Q K^T ----------------
        float acc_s[2][4][4];
#pragma unroll
        for (int mf = 0; mf < 2; mf++)
#pragma unroll
            for (int nf = 0; nf < 4; nf++)
#pragma unroll
                for (int ci = 0; ci < 4; ci++) acc_s[mf][nf][ci] = 0.f;

#pragma unroll
        for (int dc = 0; dc < 4; dc++)
#pragma unroll
            for (int ks = 0; ks < 4; ks++) {
                const uint32 kb = dc * 128 + ks * 32;
                uint32 ah[2][4], bh[4][2];
#pragma unroll
                for (int mf = 0; mf < 2; mf++)
                    LDSM4(ah[mf][0], ah[mf][1], ah[mf][2], ah[mf][3],
                          smb + SQ_ + (wm * 32 + mf * 16) * 528 + aoffQ + kb);
#pragma unroll
                for (int nfp = 0; nfp < 2; nfp++)
                    LDSM4(bh[2 * nfp][0], bh[2 * nfp][1],
                          bh[2 * nfp + 1][0], bh[2 * nfp + 1][1],
                          smb + SK_ + (wn * 32 + nfp * 16) * 528 + boffK + kb);
#pragma unroll
                for (int mf = 0; mf < 2; mf++)
#pragma unroll
                    for (int nf = 0; nf < 4; nf++)
                        mma_f16(acc_s[mf][nf], ah[mf], bh[nf]);
            }

        // ---------------- scale + mask + row-max ----------------
        float pm[4] = {-1e30f, -1e30f, -1e30f, -1e30f};
#pragma unroll
        for (int mf = 0; mf < 2; mf++)
#pragma unroll
            for (int nf = 0; nf < 4; nf++)
#pragma unroll
                for (int ci = 0; ci < 4; ci++) {
                    float s = acc_s[mf][nf][ci] * 0.0625f;
                    if (diag) {
                        int qg = q0 + wm * 32 + mf * 16 + gr + (ci >> 1) * 8;
                        int kg = kt * 128 + wn * 32 + nf * 8 + 2 * tc + (ci & 1);
                        if (kg > qg) s = -1e30f;
                    }
                    acc_s[mf][nf][ci] = s;
                    int ri = mf * 2 + (ci >> 1);
                    pm[ri] = fmaxf(pm[ri], s);
                }
#pragma unroll
        for (int i = 0; i < 4; i++) {
            pm[i] = fmaxf(pm[i], __shfl_xor_sync(~0u, pm[i], 1));
            pm[i] = fmaxf(pm[i], __shfl_xor_sync(~0u, pm[i], 2));
        }
        if (tc == 0) {
#pragma unroll
            for (int i = 0; i < 4; i++) {
                int row = wm * 32 + (i >> 1) * 16 + (i & 1) * 8 + gr;
                pmax[row * 4 + wn] = pm[i];
            }
        }
        __syncthreads();   // pmax visible

        float alpha[4];
#pragma unroll
        for (int i = 0; i < 4; i++) {
            int row = wm * 32 + (i >> 1) * 16 + (i & 1) * 8 + gr;
            float mt = fmaxf(fmaxf(pmax[row * 4 + 0], pmax[row * 4 + 1]),
                             fmaxf(pmax[row * 4 + 2], pmax[row * 4 + 3]));
            float m_new = fmaxf(m[i], mt);
            alpha[i] = __expf(m[i] - m_new);
            m[i] = m_new;
            l[i] *= alpha[i];
        }
#pragma unroll
        for (int mf = 0; mf < 2; mf++)
#pragma unroll
            for (int nf = 0; nf < 8; nf++)
#pragma unroll
                for (int ci = 0; ci < 4; ci++)
                    acc_o[mf][nf][ci] *= alpha[mf * 2 + (ci >> 1)];

        // ---------------- exp -> P (fp16) into smem ----------------
#pragma unroll
        for (int mf = 0; mf < 2; mf++)
#pragma unroll
            for (int nf = 0; nf < 4; nf++)
#pragma unroll
                for (int h = 0; h < 2; h++) {
                    int ri = mf * 2 + h;
                    float p0 = __expf(acc_s[mf][nf][h * 2 + 0] - m[ri]);
                    float p1 = __expf(acc_s[mf][nf][h * 2 + 1] - m[ri]);
                    l[ri] += p0 + p1;
                    int row = wm * 32 + mf * 16 + h * 8 + gr;
                    p32[row * 68 + wn * 16 + nf * 4 + tc] =
                        pk(__float2half(p0), __float2half(p1));
                }
        CPA_WAIT(0);       // V landed (hidden under S + softmax)
        __syncthreads();   // P + V visible

        // ---------------- PV (V frags via ldmatrix.trans) ----------------
#pragma unroll
        for (int kc = 0; kc < 2; kc++)
#pragma unroll
            for (int ks = 0; ks < 4; ks++) {
                const uint32 sb_ = (kc * 64 + ks * 16) * 528;
                const uint32 pb_ = kc * 128 + ks * 32;
                uint32 ah[2][4], bh[8][2];
#pragma unroll
                for (int mf = 0; mf < 2; mf++)
                    LDSM4(ah[mf][0], ah[mf][1], ah[mf][2], ah[mf][3],
                          smb + SP_ + (wm * 32 + mf * 16) * 272 + aoffP + pb_);
#pragma unroll
                for (int nfp = 0; nfp < 4; nfp++)
                    LDSM4T(bh[2 * nfp][0], bh[2 * nfp][1],
                           bh[2 * nfp + 1][0], bh[2 * nfp + 1][1],
                           smb + SV_ + sb_ + boffV + wn * 128 + nfp * 32);
#pragma unroll
                for (int mf = 0; mf < 2; mf++)
#pragma unroll
                    for (int nf = 0; nf < 8; nf++)
                        mma_f16(acc_o[mf][nf], ah[mf], bh[nf]);
            }
    }

    // ---------------- epilogue: reduce l, write partials ----------------
#pragma unroll
    for (int i = 0; i < 4; i++) {
        l[i] += __shfl_xor_sync(~0u, l[i], 1);
        l[i] += __shfl_xor_sync(~0u, l[i], 2);
    }
    __syncthreads();   // last PV reads + pmax reads done before reuse
    if (tc == 0) {
#pragma unroll
        for (int i = 0; i < 4; i++) {
            int row = wm * 32 + (i >> 1) * 16 + (i & 1) * 8 + gr;
            pmax[row * 4 + wn] = l[i];
        }
    }
    __syncthreads();

    const size_t pb = ((size_t)(b * 64 + qi) * 4 + c) * 64;
#pragma unroll
    for (int i = 0; i < 4; i++) {
        int row = wm * 32 + (i >> 1) * 16 + (i & 1) * 8 + gr;
        if (wn == 0 && tc == 0) {
            float lr = pmax[row * 4 + 0] + pmax[row * 4 + 1] +
                       pmax[row * 4 + 2] + pmax[row * 4 + 3];
            MPart[pb + row] = m[i];
            LPart[pb + row] = lr;
        }
    }
#pragma unroll
    for (int mf = 0; mf < 2; mf++)
#pragma unroll
        for (int h = 0; h < 2; h++) {
            int row = wm * 32 + mf * 16 + h * 8 + gr;
            float* orow = OPart + (pb + row) * 256;
#pragma unroll
            for (int nf = 0; nf < 8; nf++) {
                float2 v = make_float2(acc_o[mf][nf][h * 2 + 0],
                                       acc_o[mf][nf][h * 2 + 1]);
                *(float2*)(orow + wn * 64 + nf * 8 + 2 * tc) = v;
            }
        }
}

// ============================ kernel 5: combine =======================
__global__ __launch_bounds__(256) void combine_k(float* __restrict__ out) {
    const int t = threadIdx.x;
    const int R = blockIdx.x * 4 + (t >> 6);   // = q*2 + b
    const int q = R >> 1, b = R & 1;
    const int qi = q >> 6, r = q & 63;
    const int nc = (qi >> 4) + 1;
    const size_t cb = ((size_t)(b * 64 + qi) * 4) * 64 + r;

    float mx = -INFINITY;
    for (int c = 0; c < nc; c++) mx = fmaxf(mx, MPart[cb + (size_t)c * 64]);
    float w[4];
    float denom = 0.f;
    for (int c = 0; c < nc; c++) {
        w[c] = __expf(MPart[cb + (size_t)c * 64] - mx);
        denom += w[c] * LPart[cb + (size_t)c * 64];
    }
    const float inv = 1.f / denom;

    const int d = (t & 63) * 4;
    float4 acc = make_float4(0.f, 0.f, 0.f, 0.f);
    for (int c = 0; c < nc; c++) {
        const float4 v = *(const float4*)
            (OPart + (cb + (size_t)c * 64) * 256 + d);
        acc.x += w[c] * v.x; acc.y += w[c] * v.y;
        acc.z += w[c] * v.z; acc.w += w[c] * v.w;
    }
    acc.x *= inv; acc.y *= inv; acc.z *= inv; acc.w *= inv;
    *(float4*)(out + (size_t)R * 256 + d) = acc;
}

// ============================ launch ==================================
extern "C" void kernel_launch(void* const* d_in, const int* in_sizes, int n_in,
                              void* d_out, int out_size) {
    const float* x  = (const float*)d_in[0];
    const float* Wq = (const float*)d_in[2];
    const float* Wk = (const float*)d_in[3];
    const float* Wv = (const float*)d_in[4];
    float* out = (float*)d_out;

    cudaFuncSetAttribute(proj_mma, cudaFuncAttributeMaxDynamicSharedMemorySize, SMEM_GEMM);
    cudaFuncSetAttribute(fa_mma,   cudaFuncAttributeMaxDynamicSharedMemorySize, FSZ);

    cvt_xw<<<2816, 256>>>(x, Wq, Wk, Wv);
    proj_mma<<<dim3(128, 3), 256, SMEM_GEMM>>>();
    fa_mma<<<dim3(160, 2), 256, FSZ>>>();
    combine_k<<<2048, 256>>>(out);
}

// round 16
// speedup vs baseline: 1.0447x; 1.0134x over previous
#include <cuda_runtime.h>
#include <cuda_fp16.h>
#include <math.h>
#include <stdint.h>

typedef __half f16;
typedef unsigned int uint32;

// ============================ scratch =================================
__device__ f16   Xh[8192 * 1024];
__device__ f16   Wth[3 * 256 * 1024], Wtl[3 * 256 * 1024];   // W^T [proj][n][k]
__device__ f16   Qh[2 * 4096 * 256];
__device__ f16   Kh[2 * 4096 * 256];
__device__ f16   Vh[2 * 4096 * 256];
__device__ float OPart[2ull * 64 * 4 * 64 * 256];            // split-K partials
__device__ float MPart[2 * 64 * 4 * 64];
__device__ float LPart[2 * 64 * 4 * 64];

// ============================ helpers =================================
__device__ __forceinline__ void split2(float x, f16& h, f16& l) {
    h = __float2half(x);
    l = __float2half(x - __half2float(h));
}
__device__ __forceinline__ uint32 pk(f16 a, f16 b) {
    __half2 v(a, b);
    return *(uint32*)&v;
}
__device__ __forceinline__ void mma_f16(float c[4], const uint32 a[4],
                                        const uint32 b[2]) {
    asm volatile(
        "mma.sync.aligned.m16n8k16.row.col.f32.f16.f16.f32 "
        "{%0,%1,%2,%3}, {%4,%5,%6,%7}, {%8,%9}, {%0,%1,%2,%3};"
        : "+f"(c[0]), "+f"(c[1]), "+f"(c[2]), "+f"(c[3])
        : "r"(a[0]), "r"(a[1]), "r"(a[2]), "r"(a[3]), "r"(b[0]), "r"(b[1]));
}
#define LDSM4(r0, r1, r2, r3, a)                                              \
    asm volatile("ldmatrix.sync.aligned.m8n8.x4.shared.b16 {%0,%1,%2,%3}, [%4];" \
                 : "=r"(r0), "=r"(r1), "=r"(r2), "=r"(r3) : "r"(a))
#define LDSM4T(r0, r1, r2, r3, a)                                             \
    asm volatile("ldmatrix.sync.aligned.m8n8.x4.trans.shared.b16 {%0,%1,%2,%3}, [%4];" \
                 : "=r"(r0), "=r"(r1), "=r"(r2), "=r"(r3) : "r"(a))
#define CPA16(dst, src)                                                       \
    asm volatile("cp.async.cg.shared.global [%0], [%1], 16;"                  \
                 :: "r"((uint32)(dst)), "l"(src))
#define CPA_COMMIT() asm volatile("cp.async.commit_group;")
#define CPA_WAIT(n)  asm volatile("cp.async.wait_group %0;" :: "n"(n))

// ======================================================================
// Projection GEMM: 2-pass fp16 split, cp.async double-buffered stages,
// ldmatrix fragment loads (stride 144 B = 4 words mod 32, conflict-free).
// ======================================================================
#define RS   72
#define PL   18432                  // bytes per plane
#define STG  (3 * PL)               // 55296 per stage
#define SMEM_GEMM (2 * STG)         // 110592 -> 2 CTAs/SM

__global__ __launch_bounds__(256, 2) void proj_mma() {
    extern __shared__ char smem[];
    const uint32 smb = (uint32)__cvta_generic_to_shared(smem);
    const int m0 = (blockIdx.x >> 1) * 128;
    const int nb = blockIdx.x & 1;
    const int pj = blockIdx.y;

    const f16* Ag  = Xh + (size_t)m0 * 1024;
    const f16* Bhg = Wth + pj * 262144 + (size_t)(nb * 128) * 1024;
    const f16* Blg = Wtl + pj * 262144 + (size_t)(nb * 128) * 1024;

    const int t = threadIdx.x, wid = t >> 5, lane = t & 31;
    const int wm = wid >> 2, wn = wid & 3;
    const int gr = lane >> 2, tc = lane & 3;

    // ldmatrix per-thread offsets (stride 144 B rows)
    const uint32 aoff = (lane & 15) * 144 + (lane >> 4) * 16;
    const uint32 boff = ((lane & 7) + ((lane >> 4) & 1) * 8) * 144 + ((lane >> 3) & 1) * 16;

    int row[4], c8[4];
#pragma unroll
    for (int i = 0; i < 4; i++) { int u = t + 256 * i; row[i] = u >> 3; c8[i] = u & 7; }

#define ISSUE(ch, buf) {                                                      \
    const int k0_ = (ch) * 64;                                                \
    const uint32 bb_ = smb + (buf) * STG;                                     \
    _Pragma("unroll") for (int i_ = 0; i_ < 4; i_++) {                        \
        uint32 off_ = row[i_] * 144 + c8[i_] * 16;                            \
        CPA16(bb_ + off_,          Ag  + (size_t)row[i_] * 1024 + k0_ + c8[i_] * 8); \
        CPA16(bb_ + PL + off_,     Bhg + (size_t)row[i_] * 1024 + k0_ + c8[i_] * 8); \
        CPA16(bb_ + 2 * PL + off_, Blg + (size_t)row[i_] * 1024 + k0_ + c8[i_] * 8); \
    }                                                                         \
    CPA_COMMIT(); }

    float acc[16][4];
#pragma unroll
    for (int i = 0; i < 16; i++)
#pragma unroll
        for (int j = 0; j < 4; j++) acc[i][j] = 0.f;

    ISSUE(0, 0);
    for (int ch = 0; ch < 16; ch++) {
        if (ch + 1 < 16) { ISSUE(ch + 1, (ch + 1) & 1); CPA_WAIT(1); }
        else             { CPA_WAIT(0); }
        __syncthreads();   // stage (ch&1) fully visible

        const uint32 bb = smb + (ch & 1) * STG;

#pragma unroll
        for (int ks = 0; ks < 4; ks++) {
            const uint32 kb = ks * 32;
            uint32 ah[4][4], bh[4][2], bl[4][2];
#pragma unroll
            for (int mf = 0; mf < 4; mf++)
                LDSM4(ah[mf][0], ah[mf][1], ah[mf][2], ah[mf][3],
                      bb + (wm * 64 + mf * 16) * 144 + aoff + kb);
#pragma unroll
            for (int nfp = 0; nfp < 2; nfp++) {
                LDSM4(bh[2 * nfp][0], bh[2 * nfp][1],
                      bh[2 * nfp + 1][0], bh[2 * nfp + 1][1],
                      bb + PL + (wn * 32 + nfp * 16) * 144 + boff + kb);
                LDSM4(bl[2 * nfp][0], bl[2 * nfp][1],
                      bl[2 * nfp + 1][0], bl[2 * nfp + 1][1],
                      bb + 2 * PL + (wn * 32 + nfp * 16) * 144 + boff + kb);
            }
#pragma unroll
            for (int mf = 0; mf < 4; mf++)
#pragma unroll
                for (int nf = 0; nf < 4; nf++) {
                    mma_f16(acc[mf * 4 + nf], ah[mf], bh[nf]);
                    mma_f16(acc[mf * 4 + nf], ah[mf], bl[nf]);
                }
        }
        __syncthreads();   // stage reads done before refill (ch+2)
    }
#undef ISSUE

    f16* dh = (pj == 0) ? Qh : (pj == 1) ? Kh : Vh;
#pragma unroll
    for (int mf = 0; mf < 4; mf++)
#pragma unroll
        for (int nf = 0; nf < 4; nf++)
#pragma unroll
            for (int h = 0; h < 2; h++) {
                int m = m0 + wm * 64 + mf * 16 + gr + 8 * h;
                int n = nb * 128 + wn * 32 + nf * 8 + 2 * tc;
                int s = m >> 1, b = m & 1;
                float v0 = acc[mf * 4 + nf][2 * h];
                float v1 = acc[mf * 4 + nf][2 * h + 1];
                size_t o = ((size_t)b * 4096 + s) * 256 + n;
                *(uint32*)(dh + o) = pk(__float2half(v0), __float2half(v1));
            }
}

// ============== kernel 1: merged convert X + convert/transpose W ======
__global__ __launch_bounds__(256) void cvt_xw(const float* __restrict__ X,
                                              const float* __restrict__ Wq,
                                              const float* __restrict__ Wk,
                                              const float* __restrict__ Wv) {
    const int t = threadIdx.x;
    const int bid = blockIdx.x;
    if (bid < 2048) {
        const int N4 = 8192 * 1024 / 4;
        for (int i = bid * 256 + t; i < N4; i += 2048 * 256) {
            float4 x = ((const float4*)X)[i];
            ((uint2*)Xh)[i] = make_uint2(
                pk(__float2half(x.x), __float2half(x.y)),
                pk(__float2half(x.z), __float2half(x.w)));
        }
    } else {
        __shared__ float tile[32][33];
        const int wb = bid - 2048;
        const int pj = wb >> 8;
        const int rem = wb & 255;
        const int k0 = (rem >> 3) * 32;
        const int n0 = (rem & 7) * 32;
        const float* W = (pj == 0) ? Wq : (pj == 1) ? Wk : Wv;
        const int tx = t & 31, ty = t >> 5;
#pragma unroll
        for (int i = 0; i < 4; i++)
            tile[ty + 8 * i][tx] = W[(k0 + ty + 8 * i) * 256 + n0 + tx];
        __syncthreads();
#pragma unroll
        for (int i = 0; i < 4; i++) {
            int n = n0 + ty + 8 * i;
            f16 h, l;
            split2(tile[tx][ty + 8 * i], h, l);
            Wth[pj * 262144 + n * 1024 + k0 + tx] = h;
            Wtl[pj * 262144 + n * 1024 + k0 + tx] = l;
        }
    }
}

// ======================================================================
// Kernel 4: fused flash attention — R12 form + direct-write epilogue for
// single-chunk CTAs (qi < 16: out = o/l, identical math to combine nc=1).
// ======================================================================
#define SQ_  0                      // Q: 64 rows x 528 B   = 33792
#define SK_  33792                  // K: 128 rows x 528 B  = 67584
#define SV_  101376                 // V: 128 rows x 528 B  = 67584
#define SP_  168960                 // P: 64 x 272 B        = 17408
#define SMX_ 186368                 // 64 x 4 floats
#define FSZ  187392

__global__ __launch_bounds__(256) void fa_mma(float* __restrict__ outp) {
    extern __shared__ char sm[];
    const int t = threadIdx.x, wid = t >> 5, lane = t & 31;
    const int wm = wid >> 2, wn = wid & 3;
    const int gr = lane >> 2, tc = lane & 3;
    const int b = blockIdx.y;
    const uint32 smb = (uint32)__cvta_generic_to_shared(sm);

    const uint32 aoffQ = (lane & 15) * 528 + (lane >> 4) * 16;
    const uint32 aoffP = (lane & 15) * 272 + (lane >> 4) * 16;
    const uint32 boffK = ((lane & 7) + ((lane >> 4) & 1) * 8) * 528 + ((lane >> 3) & 1) * 16;
    const uint32 boffV = ((lane & 7) + ((lane >> 3) & 1) * 8) * 528 + ((lane >> 4) & 1) * 16;

    // chunk decode (reversed: biggest qi first); CHUNK = 8 key-tiles
    const int n = 159 - blockIdx.x;
    int qi, c;
    if (n < 16)      { qi = n;                  c = 0; }
    else if (n < 48) { int m_ = n - 16; qi = 16 + (m_ >> 1); c = m_ & 1; }
    else if (n < 96) { int m_ = n - 48; qi = 32 + m_ / 3;    c = m_ % 3; }
    else             { int m_ = n - 96; qi = 48 + (m_ >> 2); c = m_ & 3; }

    const int kt_diag = qi >> 1;
    const int kt0 = c * 8;
    const int kt1 = min(kt0 + 8, kt_diag + 1);
    const int q0 = qi * 64;

    uint32* p32 = (uint32*)(sm + SP_);
    float* pmax = (float*)(sm + SMX_);

    // ---- load Q once (64 x 256 f16) ----
#pragma unroll
    for (int i = 0; i < 8; i++) {
        int u = t + 256 * i, row = u >> 5, c16 = u & 31;
        *(float4*)(sm + SQ_ + row * 528 + c16 * 16) =
            *(const float4*)(Qh + ((size_t)(b * 4096 + q0 + row)) * 256 + c16 * 8);
    }

    float acc_o[2][8][4];
#pragma unroll
    for (int mf = 0; mf < 2; mf++)
#pragma unroll
        for (int nf = 0; nf < 8; nf++)
#pragma unroll
            for (int ci = 0; ci < 4; ci++) acc_o[mf][nf][ci] = 0.f;
    float m[4] = {-INFINITY, -INFINITY, -INFINITY, -INFINITY};
    float l[4] = {0.f, 0.f, 0.f, 0.f};

    for (int kt = kt0; kt < kt1; kt++) {
        const bool diag = (kt == kt_diag);

        __syncthreads();   // prior iter's smem reads done (covers Q stores, iter 0)
#pragma unroll
        for (int i = 0; i < 16; i++) {
            int u = t + 256 * i, row = u >> 5, c16 = u & 31;
            CPA16(smb + SK_ + row * 528 + c16 * 16,
                  Kh + ((size_t)(b * 4096 + kt * 128 + row)) * 256 + c16 * 8);
        }
        CPA_COMMIT();
#pragma unroll
        for (int i = 0; i < 16; i++) {
            int u = t + 256 * i, row = u >> 5, c16 = u & 31;
            CPA16(smb + SV_ + row * 528 + c16 * 16,
                  Vh + ((size_t)(b * 4096 + kt * 128 + row)) * 256 + c16 * 8);
        }
        CPA_COMMIT();
        CPA_WAIT(1);       // K landed; V still in flight
        __syncthreads();

        // ---------------- S = Q K^T ----------------
        float acc_s[2][4][4];
#pragma unroll
        for (int mf = 0; mf < 2; mf++)
#pragma unroll
            for (int nf = 0; nf < 4; nf++)
#pragma unroll
                for (int ci = 0; ci < 4; ci++) acc_s[mf][nf][ci] = 0.f;

#pragma unroll
        for (int dc = 0; dc < 4; dc++)
#pragma unroll
            for (int ks = 0; ks < 4; ks++) {
                const uint32 kb = dc * 128 + ks * 32;
                uint32 ah[2][4], bh[4][2];
#pragma unroll
                for (int mf = 0; mf < 2; mf++)
                    LDSM4(ah[mf][0], ah[mf][1], ah[mf][2], ah[mf][3],
                          smb + SQ_ + (wm * 32 + mf * 16) * 528 + aoffQ + kb);
#pragma unroll
                for (int nfp = 0; nfp < 2; nfp++)
                    LDSM4(bh[2 * nfp][0], bh[2 * nfp][1],
                          bh[2 * nfp + 1][0], bh[2 * nfp + 1][1],
                          smb + SK_ + (wn * 32 + nfp * 16) * 528 + boffK + kb);
#pragma unroll
                for (int mf = 0; mf < 2; mf++)
#pragma unroll
                    for (int nf = 0; nf < 4; nf++)
                        mma_f16(acc_s[mf][nf], ah[mf], bh[nf]);
            }

        // ---------------- scale + mask + row-max ----------------
        float pm[4] = {-1e30f, -1e30f, -1e30f, -1e30f};
#pragma unroll
        for (int mf = 0; mf < 2; mf++)
#pragma unroll
            for (int nf = 0; nf < 4; nf++)
#pragma unroll
                for (int ci = 0; ci < 4; ci++) {
                    float s = acc_s[mf][nf][ci] * 0.0625f;
                    if (diag) {
                        int qg = q0 + wm * 32 + mf * 16 + gr + (ci >> 1) * 8;
                        int kg = kt * 128 + wn * 32 + nf * 8 + 2 * tc + (ci & 1);
                        if (kg > qg) s = -1e30f;
                    }
                    acc_s[mf][nf][ci] = s;
                    int ri = mf * 2 + (ci >> 1);
                    pm[ri] = fmaxf(pm[ri], s);
                }
#pragma unroll
        for (int i = 0; i < 4; i++) {
            pm[i] = fmaxf(pm[i], __shfl_xor_sync(~0u, pm[i], 1));
            pm[i] = fmaxf(pm[i], __shfl_xor_sync(~0u, pm[i], 2));
        }
        if (tc == 0) {
#pragma unroll
            for (int i = 0; i < 4; i++) {
                int row = wm * 32 + (i >> 1) * 16 + (i & 1) * 8 + gr;
                pmax[row * 4 + wn] = pm[i];
            }
        }
        __syncthreads();   // pmax visible

        float alpha[4];
#pragma unroll
        for (int i = 0; i < 4; i++) {
            int row = wm * 32 + (i >> 1) * 16 + (i & 1) * 8 + gr;
            float mt = fmaxf(fmaxf(pmax[row * 4 + 0], pmax[row * 4 + 1]),
                             fmaxf(pmax[row * 4 + 2], pmax[row * 4 + 3]));
            float m_new = fmaxf(m[i], mt);
            alpha[i] = __expf(m[i] - m_new);
            m[i] = m_new;
            l[i] *= alpha[i];
        }
#pragma unroll
        for (int mf = 0; mf < 2; mf++)
#pragma unroll
            for (int nf = 0; nf < 8; nf++)
#pragma unroll
                for (int ci = 0; ci < 4; ci++)
                    acc_o[mf][nf][ci] *= alpha[mf * 2 + (ci >> 1)];

        // ---------------- exp -> P (fp16) into smem ----------------
#pragma unroll
        for (int mf = 0; mf < 2; mf++)
#pragma unroll
            for (int nf = 0; nf < 4; nf++)
#pragma unroll
                for (int h = 0; h < 2; h++) {
                    int ri = mf * 2 + h;
                    float p0 = __expf(acc_s[mf][nf][h * 2 + 0] - m[ri]);
                    float p1 = __expf(acc_s[mf][nf][h * 2 + 1] - m[ri]);
                    l[ri] += p0 + p1;
                    int row = wm * 32 + mf * 16 + h * 8 + gr;
                    p32[row * 68 + wn * 16 + nf * 4 + tc] =
                        pk(__float2half(p0), __float2half(p1));
                }
        CPA_WAIT(0);       // V landed (hidden under S + softmax)
        __syncthreads();   // P + V visible

        // ---------------- PV (V frags via ldmatrix.trans) ----------------
#pragma unroll
        for (int kc = 0; kc < 2; kc++)
#pragma unroll
            for (int ks = 0; ks < 4; ks++) {
                const uint32 sb_ = (kc * 64 + ks * 16) * 528;
                const uint32 pb_ = kc * 128 + ks * 32;
                uint32 ah[2][4], bh[8][2];
#pragma unroll
                for (int mf = 0; mf < 2; mf++)
                    LDSM4(ah[mf][0], ah[mf][1], ah[mf][2], ah[mf][3],
                          smb + SP_ + (wm * 32 + mf * 16) * 272 + aoffP + pb_);
#pragma unroll
                for (int nfp = 0; nfp < 4; nfp++)
                    LDSM4T(bh[2 * nfp][0], bh[2 * nfp][1],
                           bh[2 * nfp + 1][0], bh[2 * nfp + 1][1],
                           smb + SV_ + sb_ + boffV + wn * 128 + nfp * 32);
#pragma unroll
                for (int mf = 0; mf < 2; mf++)
#pragma unroll
                    for (int nf = 0; nf < 8; nf++)
                        mma_f16(acc_o[mf][nf], ah[mf], bh[nf]);
            }
    }

    // ---------------- epilogue ----------------
#pragma unroll
    for (int i = 0; i < 4; i++) {
        l[i] += __shfl_xor_sync(~0u, l[i], 1);
        l[i] += __shfl_xor_sync(~0u, l[i], 2);
    }
    __syncthreads();   // last PV reads + pmax reads done before reuse
    if (tc == 0) {
#pragma unroll
        for (int i = 0; i < 4; i++) {
            int row = wm * 32 + (i >> 1) * 16 + (i & 1) * 8 + gr;
            pmax[row * 4 + wn] = l[i];
        }
    }
    __syncthreads();

    // per-row total l (all threads need it for direct write)
    float inv[4];
#pragma unroll
    for (int i = 0; i < 4; i++) {
        int row = wm * 32 + (i >> 1) * 16 + (i & 1) * 8 + gr;
        float lr = pmax[row * 4 + 0] + pmax[row * 4 + 1] +
                   pmax[row * 4 + 2] + pmax[row * 4 + 3];
        inv[i] = 1.f / lr;
        if (qi >= 16 && wn == 0 && tc == 0) {
            const size_t pb_ = ((size_t)(b * 64 + qi) * 4 + c) * 64;
            MPart[pb_ + row] = m[i];
            LPart[pb_ + row] = lr;
        }
    }

    if (qi < 16) {
        // single-chunk: write normalized output directly (== combine nc=1)
#pragma unroll
        for (int mf = 0; mf < 2; mf++)
#pragma unroll
            for (int h = 0; h < 2; h++) {
                int row = wm * 32 + mf * 16 + h * 8 + gr;
                float iv = inv[mf * 2 + h];
                float* orow = outp + ((size_t)((q0 + row) * 2 + b)) * 256;
#pragma unroll
                for (int nf = 0; nf < 8; nf++) {
                    float2 v = make_float2(acc_o[mf][nf][h * 2 + 0] * iv,
                                           acc_o[mf][nf][h * 2 + 1] * iv);
                    *(float2*)(orow + wn * 64 + nf * 8 + 2 * tc) = v;
                }
            }
    } else {
        const size_t pb_ = ((size_t)(b * 64 + qi) * 4 + c) * 64;
#pragma unroll
        for (int mf = 0; mf < 2; mf++)
#pragma unroll
            for (int h = 0; h < 2; h++) {
                int row = wm * 32 + mf * 16 + h * 8 + gr;
                float* orow = OPart + (pb_ + row) * 256;
#pragma unroll
                for (int nf = 0; nf < 8; nf++) {
                    float2 v = make_float2(acc_o[mf][nf][h * 2 + 0],
                                           acc_o[mf][nf][h * 2 + 1]);
                    *(float2*)(orow + wn * 64 + nf * 8 + 2 * tc) = v;
                }
            }
    }
}

// ============================ kernel 5: combine (qi >= 16 only) =======
__global__ __launch_bounds__(256) void combine_k(float* __restrict__ out) {
    const int t = threadIdx.x;
    const int R = 2048 + blockIdx.x * 4 + (t >> 6);   // q >= 1024
    const int q = R >> 1, b = R & 1;
    const int qi = q >> 6, r = q & 63;
    const int nc = (qi >> 4) + 1;
    const size_t cb = ((size_t)(b * 64 + qi) * 4) * 64 + r;

    float mx = -INFINITY;
    for (int c = 0; c < nc; c++) mx = fmaxf(mx, MPart[cb + (size_t)c * 64]);
    float w[4];
    float denom = 0.f;
    for (int c = 0; c < nc; c++) {
        w[c] = __expf(MPart[cb + (size_t)c * 64] - mx);
        denom += w[c] * LPart[cb + (size_t)c * 64];
    }
    const float inv = 1.f / denom;

    const int d = (t & 63) * 4;
    float4 acc = make_float4(0.f, 0.f, 0.f, 0.f);
    for (int c = 0; c < nc; c++) {
        const float4 v = *(const float4*)
            (OPart + (cb + (size_t)c * 64) * 256 + d);
        acc.x += w[c] * v.x; acc.y += w[c] * v.y;
        acc.z += w[c] * v.z; acc.w += w[c] * v.w;
    }
    acc.x *= inv; acc.y *= inv; acc.z *= inv; acc.w *= inv;
    *(float4*)(out + (size_t)R * 256 + d) = acc;
}

// ============================ launch ==================================
extern "C" void kernel_launch(void* const* d_in, const int* in_sizes, int n_in,
                              void* d_out, int out_size) {
    const float* x  = (const float*)d_in[0];
    const float* Wq = (const float*)d_in[2];
    const float* Wk = (const float*)d_in[3];
    const float* Wv = (const float*)d_in[4];
    float* out = (float*)d_out;

    cudaFuncSetAttribute(proj_mma, cudaFuncAttributeMaxDynamicSharedMemorySize, SMEM_GEMM);
    cudaFuncSetAttribute(fa_mma,   cudaFuncAttributeMaxDynamicSharedMemorySize, FSZ);

    cvt_xw<<<2816, 256>>>(x, Wq, Wk, Wv);
    proj_mma<<<dim3(128, 3), 256, SMEM_GEMM>>>();
    fa_mma<<<dim3(160, 2), 256, FSZ>>>(out);
    combine_k<<<1536, 256>>>(out);
}

// round 17
// speedup vs baseline: 1.0883x; 1.0417x over previous
#include <cuda_runtime.h>
#include <cuda_fp16.h>
#include <math.h>
#include <stdint.h>

typedef __half f16;
typedef unsigned int uint32;

// ============================ scratch =================================
__device__ f16   Xh[8192 * 1024];
__device__ f16   Wth[3 * 256 * 1024];                        // W^T [proj][n][k]
__device__ f16   Qh[2 * 4096 * 256];
__device__ f16   Kh[2 * 4096 * 256];
__device__ f16   Vh[2 * 4096 * 256];
__device__ float OPart[2ull * 64 * 4 * 64 * 256];            // split-K partials
__device__ float MPart[2 * 64 * 4 * 64];
__device__ float LPart[2 * 64 * 4 * 64];

// ============================ helpers =================================
__device__ __forceinline__ uint32 pk(f16 a, f16 b) {
    __half2 v(a, b);
    return *(uint32*)&v;
}
__device__ __forceinline__ void mma_f16(float c[4], const uint32 a[4],
                                        const uint32 b[2]) {
    asm volatile(
        "mma.sync.aligned.m16n8k16.row.col.f32.f16.f16.f32 "
        "{%0,%1,%2,%3}, {%4,%5,%6,%7}, {%8,%9}, {%0,%1,%2,%3};"
        : "+f"(c[0]), "+f"(c[1]), "+f"(c[2]), "+f"(c[3])
        : "r"(a[0]), "r"(a[1]), "r"(a[2]), "r"(a[3]), "r"(b[0]), "r"(b[1]));
}
#define LDSM4(r0, r1, r2, r3, a)                                              \
    asm volatile("ldmatrix.sync.aligned.m8n8.x4.shared.b16 {%0,%1,%2,%3}, [%4];" \
                 : "=r"(r0), "=r"(r1), "=r"(r2), "=r"(r3) : "r"(a))
#define LDSM4T(r0, r1, r2, r3, a)                                             \
    asm volatile("ldmatrix.sync.aligned.m8n8.x4.trans.shared.b16 {%0,%1,%2,%3}, [%4];" \
                 : "=r"(r0), "=r"(r1), "=r"(r2), "=r"(r3) : "r"(a))
#define CPA16(dst, src)                                                       \
    asm volatile("cp.async.cg.shared.global [%0], [%1], 16;"                  \
                 :: "r"((uint32)(dst)), "l"(src))
#define CPA_COMMIT() asm volatile("cp.async.commit_group;")
#define CPA_WAIT(n)  asm volatile("cp.async.wait_group %0;" :: "n"(n))

// ======================================================================
// Projection GEMM: plain fp16 (1-pass), cp.async double-buffered stages,
// ldmatrix fragments. Stage = A(128x64) + B(128x64): 36.9 KB -> 3 CTAs/SM.
// ======================================================================
#define PL   18432                  // bytes per plane
#define STG  (2 * PL)               // 36864 per stage
#define SMEM_GEMM (2 * STG)         // 73728 -> 3 CTAs/SM

__global__ __launch_bounds__(256, 3) void proj_mma() {
    extern __shared__ char smem[];
    const uint32 smb = (uint32)__cvta_generic_to_shared(smem);
    const int m0 = (blockIdx.x >> 1) * 128;
    const int nb = blockIdx.x & 1;
    const int pj = blockIdx.y;

    const f16* Ag  = Xh + (size_t)m0 * 1024;
    const f16* Bhg = Wth + pj * 262144 + (size_t)(nb * 128) * 1024;

    const int t = threadIdx.x, wid = t >> 5, lane = t & 31;
    const int wm = wid >> 2, wn = wid & 3;
    const int gr = lane >> 2, tc = lane & 3;

    // ldmatrix per-thread offsets (stride 144 B rows)
    const uint32 aoff = (lane & 15) * 144 + (lane >> 4) * 16;
    const uint32 boff = ((lane & 7) + ((lane >> 4) & 1) * 8) * 144 + ((lane >> 3) & 1) * 16;

    int row[4], c8[4];
#pragma unroll
    for (int i = 0; i < 4; i++) { int u = t + 256 * i; row[i] = u >> 3; c8[i] = u & 7; }

#define ISSUE(ch, buf) {                                                      \
    const int k0_ = (ch) * 64;                                                \
    const uint32 bb_ = smb + (buf) * STG;                                     \
    _Pragma("unroll") for (int i_ = 0; i_ < 4; i_++) {                        \
        uint32 off_ = row[i_] * 144 + c8[i_] * 16;                            \
        CPA16(bb_ + off_,      Ag  + (size_t)row[i_] * 1024 + k0_ + c8[i_] * 8); \
        CPA16(bb_ + PL + off_, Bhg + (size_t)row[i_] * 1024 + k0_ + c8[i_] * 8); \
    }                                                                         \
    CPA_COMMIT(); }

    float acc[16][4];
#pragma unroll
    for (int i = 0; i < 16; i++)
#pragma unroll
        for (int j = 0; j < 4; j++) acc[i][j] = 0.f;

    ISSUE(0, 0);
    for (int ch = 0; ch < 16; ch++) {
        if (ch + 1 < 16) { ISSUE(ch + 1, (ch + 1) & 1); CPA_WAIT(1); }
        else             { CPA_WAIT(0); }
        __syncthreads();   // stage (ch&1) fully visible

        const uint32 bb = smb + (ch & 1) * STG;

#pragma unroll
        for (int ks = 0; ks < 4; ks++) {
            const uint32 kb = ks * 32;
            uint32 ah[4][4], bh[4][2];
#pragma unroll
            for (int mf = 0; mf < 4; mf++)
                LDSM4(ah[mf][0], ah[mf][1], ah[mf][2], ah[mf][3],
                      bb + (wm * 64 + mf * 16) * 144 + aoff + kb);
#pragma unroll
            for (int nfp = 0; nfp < 2; nfp++)
                LDSM4(bh[2 * nfp][0], bh[2 * nfp][1],
                      bh[2 * nfp + 1][0], bh[2 * nfp + 1][1],
                      bb + PL + (wn * 32 + nfp * 16) * 144 + boff + kb);
#pragma unroll
            for (int mf = 0; mf < 4; mf++)
#pragma unroll
                for (int nf = 0; nf < 4; nf++)
                    mma_f16(acc[mf * 4 + nf], ah[mf], bh[nf]);
        }
        __syncthreads();   // stage reads done before refill (ch+2)
    }
#undef ISSUE

    f16* dh = (pj == 0) ? Qh : (pj == 1) ? Kh : Vh;
#pragma unroll
    for (int mf = 0; mf < 4; mf++)
#pragma unroll
        for (int nf = 0; nf < 4; nf++)
#pragma unroll
            for (int h = 0; h < 2; h++) {
                int m = m0 + wm * 64 + mf * 16 + gr + 8 * h;
                int n = nb * 128 + wn * 32 + nf * 8 + 2 * tc;
                int s = m >> 1, b = m & 1;
                float v0 = acc[mf * 4 + nf][2 * h];
                float v1 = acc[mf * 4 + nf][2 * h + 1];
                size_t o = ((size_t)b * 4096 + s) * 256 + n;
                *(uint32*)(dh + o) = pk(__float2half(v0), __float2half(v1));
            }
}

// ============== kernel 1: merged convert X + convert/transpose W ======
__global__ __launch_bounds__(256) void cvt_xw(const float* __restrict__ X,
                                              const float* __restrict__ Wq,
                                              const float* __restrict__ Wk,
                                              const float* __restrict__ Wv) {
    const int t = threadIdx.x;
    const int bid = blockIdx.x;
    if (bid < 2048) {
        const int N4 = 8192 * 1024 / 4;
        for (int i = bid * 256 + t; i < N4; i += 2048 * 256) {
            float4 x = ((const float4*)X)[i];
            ((uint2*)Xh)[i] = make_uint2(
                pk(__float2half(x.x), __float2half(x.y)),
                pk(__float2half(x.z), __float2half(x.w)));
        }
    } else {
        __shared__ float tile[32][33];
        const int wb = bid - 2048;
        const int pj = wb >> 8;
        const int rem = wb & 255;
        const int k0 = (rem >> 3) * 32;
        const int n0 = (rem & 7) * 32;
        const float* W = (pj == 0) ? Wq : (pj == 1) ? Wk : Wv;
        const int tx = t & 31, ty = t >> 5;
#pragma unroll
        for (int i = 0; i < 4; i++)
            tile[ty + 8 * i][tx] = W[(k0 + ty + 8 * i) * 256 + n0 + tx];
        __syncthreads();
#pragma unroll
        for (int i = 0; i < 4; i++) {
            int n = n0 + ty + 8 * i;
            Wth[pj * 262144 + n * 1024 + k0 + tx] =
                __float2half(tile[tx][ty + 8 * i]);
        }
    }
}

// ======================================================================
// Kernel 4: fused flash attention — R12 form + direct-write epilogue for
// single-chunk CTAs (qi < 16: out = o/l, identical math to combine nc=1).
// ======================================================================
#define SQ_  0                      // Q: 64 rows x 528 B   = 33792
#define SK_  33792                  // K: 128 rows x 528 B  = 67584
#define SV_  101376                 // V: 128 rows x 528 B  = 67584
#define SP_  168960                 // P: 64 x 272 B        = 17408
#define SMX_ 186368                 // 64 x 4 floats
#define FSZ  187392

__global__ __launch_bounds__(256) void fa_mma(float* __restrict__ outp) {
    extern __shared__ char sm[];
    const int t = threadIdx.x, wid = t >> 5, lane = t & 31;
    const int wm = wid >> 2, wn = wid & 3;
    const int gr = lane >> 2, tc = lane & 3;
    const int b = blockIdx.y;
    const uint32 smb = (uint32)__cvta_generic_to_shared(sm);

    const uint32 aoffQ = (lane & 15) * 528 + (lane >> 4) * 16;
    const uint32 aoffP = (lane & 15) * 272 + (lane >> 4) * 16;
    const uint32 boffK = ((lane & 7) + ((lane >> 4) & 1) * 8) * 528 + ((lane >> 3) & 1) * 16;
    const uint32 boffV = ((lane & 7) + ((lane >> 3) & 1) * 8) * 528 + ((lane >> 4) & 1) * 16;

    // chunk decode (reversed: biggest qi first); CHUNK = 8 key-tiles
    const int n = 159 - blockIdx.x;
    int qi, c;
    if (n < 16)      { qi = n;                  c = 0; }
    else if (n < 48) { int m_ = n - 16; qi = 16 + (m_ >> 1); c = m_ & 1; }
    else if (n < 96) { int m_ = n - 48; qi = 32 + m_ / 3;    c = m_ % 3; }
    else             { int m_ = n - 96; qi = 48 + (m_ >> 2); c = m_ & 3; }

    const int kt_diag = qi >> 1;
    const int kt0 = c * 8;
    const int kt1 = min(kt0 + 8, kt_diag + 1);
    const int q0 = qi * 64;

    uint32* p32 = (uint32*)(sm + SP_);
    float* pmax = (float*)(sm + SMX_);

    // ---- load Q once (64 x 256 f16) ----
#pragma unroll
    for (int i = 0; i < 8; i++) {
        int u = t + 256 * i, row = u >> 5, c16 = u & 31;
        *(float4*)(sm + SQ_ + row * 528 + c16 * 16) =
            *(const float4*)(Qh + ((size_t)(b * 4096 + q0 + row)) * 256 + c16 * 8);
    }

    float acc_o[2][8][4];
#pragma unroll
    for (int mf = 0; mf < 2; mf++)
#pragma unroll
        for (int nf = 0; nf < 8; nf++)
#pragma unroll
            for (int ci = 0; ci < 4; ci++) acc_o[mf][nf][ci] = 0.f;
    float m[4] = {-INFINITY, -INFINITY, -INFINITY, -INFINITY};
    float l[4] = {0.f, 0.f, 0.f, 0.f};

    for (int kt = kt0; kt < kt1; kt++) {
        const bool diag = (kt == kt_diag);

        __syncthreads();   // prior iter's smem reads done (covers Q stores, iter 0)
#pragma unroll
        for (int i = 0; i < 16; i++) {
            int u = t + 256 * i, row = u >> 5, c16 = u & 31;
            CPA16(smb + SK_ + row * 528 + c16 * 16,
                  Kh + ((size_t)(b * 4096 + kt * 128 + row)) * 256 + c16 * 8);
        }
        CPA_COMMIT();
#pragma unroll
        for (int i = 0; i < 16; i++) {
            int u = t + 256 * i, row = u >> 5, c16 = u & 31;
            CPA16(smb + SV_ + row * 528 + c16 * 16,
                  Vh + ((size_t)(b * 4096 + kt * 128 + row)) * 256 + c16 * 8);
        }
        CPA_COMMIT();
        CPA_WAIT(1);       // K landed; V still in flight
        __syncthreads();

        // ---------------- S = Q K^T ----------------
        float acc_s[2][4][4];
#pragma unroll
        for (int mf = 0; mf < 2; mf++)
#pragma unroll
            for (int nf = 0; nf < 4; nf++)
#pragma unroll
                for (int ci = 0; ci < 4; ci++) acc_s[mf][nf][ci] = 0.f;

#pragma unroll
        for (int dc = 0; dc < 4; dc++)
#pragma unroll
            for (int ks = 0; ks < 4; ks++) {
                const uint32 kb = dc * 128 + ks * 32;
                uint32 ah[2][4], bh[4][2];
#pragma unroll
                for (int mf = 0; mf < 2; mf++)
                    LDSM4(ah[mf][0], ah[mf][1], ah[mf][2], ah[mf][3],
                          smb + SQ_ + (wm * 32 + mf * 16) * 528 + aoffQ + kb);
#pragma unroll
                for (int nfp = 0; nfp < 2; nfp++)
                    LDSM4(bh[2 * nfp][0], bh[2 * nfp][1],
                          bh[2 * nfp + 1][0], bh[2 * nfp + 1][1],
                          smb + SK_ + (wn * 32 + nfp * 16) * 528 + boffK + kb);
#pragma unroll
                for (int mf = 0; mf < 2; mf++)
#pragma unroll
                    for (int nf = 0; nf < 4; nf++)
                        mma_f16(acc_s[mf][nf], ah[mf], bh[nf]);
            }

        // ---------------- scale + mask + row-max ----------------
        float pm[4] = {-1e30f, -1e30f, -1e30f, -1e30f};
#pragma unroll
        for (int mf = 0; mf < 2; mf++)
#pragma unroll
            for (int nf = 0; nf < 4; nf++)
#pragma unroll
                for (int ci = 0; ci < 4; ci++) {
                    float s = acc_s[mf][nf][ci] * 0.0625f;
                    if (diag) {
                        int qg = q0 + wm * 32 + mf * 16 + gr + (ci >> 1) * 8;
                        int kg = kt * 128 + wn * 32 + nf * 8 + 2 * tc + (ci & 1);
                        if (kg > qg) s = -1e30f;
                    }
                    acc_s[mf][nf][ci] = s;
                    int ri = mf * 2 + (ci >> 1);
                    pm[ri] = fmaxf(pm[ri], s);
                }
#pragma unroll
        for (int i = 0; i < 4; i++) {
            pm[i] = fmaxf(pm[i], __shfl_xor_sync(~0u, pm[i], 1));
            pm[i] = fmaxf(pm[i], __shfl_xor_sync(~0u, pm[i], 2));
        }
        if (tc == 0) {
#pragma unroll
            for (int i = 0; i < 4; i++) {
                int row = wm * 32 + (i >> 1) * 16 + (i & 1) * 8 + gr;
                pmax[row * 4 + wn] = pm[i];
            }
        }
        __syncthreads();   // pmax visible

        float alpha[4];
#pragma unroll
        for (int i = 0; i < 4; i++) {
            int row = wm * 32 + (i >> 1) * 16 + (i & 1) * 8 + gr;
            float mt = fmaxf(fmaxf(pmax[row * 4 + 0], pmax[row * 4 + 1]),
                             fmaxf(pmax[row * 4 + 2], pmax[row * 4 + 3]));
            float m_new = fmaxf(m[i], mt);
            alpha[i] = __expf(m[i] - m_new);
            m[i] = m_new;
            l[i] *= alpha[i];
        }
#pragma unroll
        for (int mf = 0; mf < 2; mf++)
#pragma unroll
            for (int nf = 0; nf < 8; nf++)
#pragma unroll
                for (int ci = 0; ci < 4; ci++)
                    acc_o[mf][nf][ci] *= alpha[mf * 2 + (ci >> 1)];

        // ---------------- exp -> P (fp16) into smem ----------------
#pragma unroll
        for (int mf = 0; mf < 2; mf++)
#pragma unroll
            for (int nf = 0; nf < 4; nf++)
#pragma unroll
                for (int h = 0; h < 2; h++) {
                    int ri = mf * 2 + h;
                    float p0 = __expf(acc_s[mf][nf][h * 2 + 0] - m[ri]);
                    float p1 = __expf(acc_s[mf][nf][h * 2 + 1] - m[ri]);
                    l[ri] += p0 + p1;
                    int row = wm * 32 + mf * 16 + h * 8 + gr;
                    p32[row * 68 + wn * 16 + nf * 4 + tc] =
                        pk(__float2half(p0), __float2half(p1));
                }
        CPA_WAIT(0);       // V landed (hidden under S + softmax)
        __syncthreads();   // P + V visible

        // ---------------- PV (V frags via ldmatrix.trans) ----------------
#pragma unroll
        for (int kc = 0; kc < 2; kc++)
#pragma unroll
            for (int ks = 0; ks < 4; ks++) {
                const uint32 sb_ = (kc * 64 + ks * 16) * 528;
                const uint32 pb_ = kc * 128 + ks * 32;
                uint32 ah[2][4], bh[8][2];
#pragma unroll
                for (int mf = 0; mf < 2; mf++)
                    LDSM4(ah[mf][0], ah[mf][1], ah[mf][2], ah[mf][3],
                          smb + SP_ + (wm * 32 + mf * 16) * 272 + aoffP + pb_);
#pragma unroll
                for (int nfp = 0; nfp < 4; nfp++)
                    LDSM4T(bh[2 * nfp][0], bh[2 * nfp][1],
                           bh[2 * nfp + 1][0], bh[2 * nfp + 1][1],
                           smb + SV_ + sb_ + boffV + wn * 128 + nfp * 32);
#pragma unroll
                for (int mf = 0; mf < 2; mf++)
#pragma unroll
                    for (int nf = 0; nf < 8; nf++)
                        mma_f16(acc_o[mf][nf], ah[mf], bh[nf]);
            }
    }

    // ---------------- epilogue ----------------
#pragma unroll
    for (int i = 0; i < 4; i++) {
        l[i] += __shfl_xor_sync(~0u, l[i], 1);
        l[i] += __shfl_xor_sync(~0u, l[i], 2);
    }
    __syncthreads();   // last PV reads + pmax reads done before reuse
    if (tc == 0) {
#pragma unroll
        for (int i = 0; i < 4; i++) {
            int row = wm * 32 + (i >> 1) * 16 + (i & 1) * 8 + gr;
            pmax[row * 4 + wn] = l[i];
        }
    }
    __syncthreads();

    // per-row total l (all threads need it for direct write)
    float inv[4];
#pragma unroll
    for (int i = 0; i < 4; i++) {
        int row = wm * 32 + (i >> 1) * 16 + (i & 1) * 8 + gr;
        float lr = pmax[row * 4 + 0] + pmax[row * 4 + 1] +
                   pmax[row * 4 + 2] + pmax[row * 4 + 3];
        inv[i] = 1.f / lr;
        if (qi >= 16 && wn == 0 && tc == 0) {
            const size_t pb_ = ((size_t)(b * 64 + qi) * 4 + c) * 64;
            MPart[pb_ + row] = m[i];
            LPart[pb_ + row] = lr;
        }
    }

    if (qi < 16) {
        // single-chunk: write normalized output directly (== combine nc=1)
#pragma unroll
        for (int mf = 0; mf < 2; mf++)
#pragma unroll
            for (int h = 0; h < 2; h++) {
                int row = wm * 32 + mf * 16 + h * 8 + gr;
                float iv = inv[mf * 2 + h];
                float* orow = outp + ((size_t)((q0 + row) * 2 + b)) * 256;
#pragma unroll
                for (int nf = 0; nf < 8; nf++) {
                    float2 v = make_float2(acc_o[mf][nf][h * 2 + 0] * iv,
                                           acc_o[mf][nf][h * 2 + 1] * iv);
                    *(float2*)(orow + wn * 64 + nf * 8 + 2 * tc) = v;
                }
            }
    } else {
        const size_t pb_ = ((size_t)(b * 64 + qi) * 4 + c) * 64;
#pragma unroll
        for (int mf = 0; mf < 2; mf++)
#pragma unroll
            for (int h = 0; h < 2; h++) {
                int row = wm * 32 + mf * 16 + h * 8 + gr;
                float* orow = OPart + (pb_ + row) * 256;
#pragma unroll
                for (int nf = 0; nf < 8; nf++) {
                    float2 v = make_float2(acc_o[mf][nf][h * 2 + 0],
                                           acc_o[mf][nf][h * 2 + 1]);
                    *(float2*)(orow + wn * 64 + nf * 8 + 2 * tc) = v;
                }
            }
    }
}

// ============================ kernel 5: combine (qi >= 16 only) =======
__global__ __launch_bounds__(256) void combine_k(float* __restrict__ out) {
    const int t = threadIdx.x;
    const int R = 2048 + blockIdx.x * 4 + (t >> 6);   // q >= 1024
    const int q = R >> 1, b = R & 1;
    const int qi = q >> 6, r = q & 63;
    const int nc = (qi >> 4) + 1;
    const size_t cb = ((size_t)(b * 64 + qi) * 4) * 64 + r;

    float mx = -INFINITY;
    for (int c = 0; c < nc; c++) mx = fmaxf(mx, MPart[cb + (size_t)c * 64]);
    float w[4];
    float denom = 0.f;
    for (int c = 0; c < nc; c++) {
        w[c] = __expf(MPart[cb + (size_t)c * 64] - mx);
        denom += w[c] * LPart[cb + (size_t)c * 64];
    }
    const float inv = 1.f / denom;

    const int d = (t & 63) * 4;
    float4 acc = make_float4(0.f, 0.f, 0.f, 0.f);
    for (int c = 0; c < nc; c++) {
        const float4 v = *(const float4*)
            (OPart + (cb + (size_t)c * 64) * 256 + d);
        acc.x += w[c] * v.x; acc.y += w[c] * v.y;
        acc.z += w[c] * v.z; acc.w += w[c] * v.w;
    }
    acc.x *= inv; acc.y *= inv; acc.z *= inv; acc.w *= inv;
    *(float4*)(out + (size_t)R * 256 + d) = acc;
}

// ============================ launch ==================================
extern "C" void kernel_launch(void* const* d_in, const int* in_sizes, int n_in,
                              void* d_out, int out_size) {
    const float* x  = (const float*)d_in[0];
    const float* Wq = (const float*)d_in[2];
    const float* Wk = (const float*)d_in[3];
    const float* Wv = (const float*)d_in[4];
    float* out = (float*)d_out;

    cudaFuncSetAttribute(proj_mma, cudaFuncAttributeMaxDynamicSharedMemorySize, SMEM_GEMM);
    cudaFuncSetAttribute(fa_mma,   cudaFuncAttributeMaxDynamicSharedMemorySize, FSZ);

    cvt_xw<<<2816, 256>>>(x, Wq, Wk, Wv);
    proj_mma<<<dim3(128, 3), 256, SMEM_GEMM>>>();
    fa_mma<<<dim3(160, 2), 256, FSZ>>>(out);
    combine_k<<<1536, 256>>>(out);
}